// round 16
// baseline (speedup 1.0000x reference)
#include <cuda_runtime.h>
#include <float.h>

// ============================================================================
// KolmogorovArnoldNetwork: exact piecewise-linear reformulation.
// R16: revert to R14 (best: 31.2us, NG=16); k_buck drops SMEM staging and
//      binary-searches g_segx directly in L2 (adjacent buckets share search
//      paths -> broadcast-coalesced loads; no smem -> full occupancy, no
//      staging prologue).
// Pipeline: k_gs(16x16) -> k_pseg(16x16) -> k_emit(17x16) -> k_buck(32x16)
//           -> k_eval(1024)
// ============================================================================

#define CHN    16
#define HID    256
#define NIV    257
#define XMAXV  64.0f
#define NG     16
#define GS     16
#define SEG_CAP 32
#define SEGMAX 8192
#define NB     8192
#define BX0    (-8.0f)
#define BINVW  512.0f       // NB / 16 range; bucket width = 2^-9 (exact)

// Scratch (device globals; no allocation)
__device__ float g_t   [CHN][HID];
__device__ int   g_idx [CHN][HID];
__device__ float g_ca1 [CHN][HID];
__device__ float g_cb1 [CHN][HID];
__device__ float g_SbA [CHN][NG][HID];
__device__ float g_SbB [CHN][NG][HID];
__device__ float g_StA [CHN][NG][HID];
__device__ float g_StB [CHN][NG][HID];
__device__ int   g_cnt [CHN][NIV];
__device__ float g_xc  [CHN][NIV][NIV];
__device__ __align__(16) float g_PQ[CHN][NIV][NIV][8];
// dense self-contained segments: {P0,P1,P2,xhi, Q0,Q1,Q2,pad}
__device__ __align__(16) float g_seg[CHN][SEGMAX][8];
__device__ float g_segx[CHN][SEGMAX];
__device__ int   g_S   [CHN];
// fat buckets: {P0,P1,P2,xhi, Q0,Q1,Q2,j_as_int_bits}
__device__ __align__(16) float g_bk[CHN][NB][8];

// ---------------------------------------------------------------------------
// K1: per (group, channel): redundant bitonic sort + this group's partials
// ---------------------------------------------------------------------------
__global__ void __launch_bounds__(256) k_gs(const float* __restrict__ W1,
                                            const float* __restrict__ B1,
                                            const float* __restrict__ W2)
{
    int g   = blockIdx.x;
    int c   = blockIdx.y;
    int tid = threadIdx.x;

    __shared__ float    key[HID];
    __shared__ unsigned idx[HID];
    __shared__ float    sw1[HID], sb1[HID];
    __shared__ float    sca0[HID], scb0[HID], sca1[HID], scb1[HID];

    float w1 = W1[c * HID + tid];
    float b1 = B1[c * HID + tid];
    sw1[tid] = w1; sb1[tid] = b1;

    float t = (w1 != 0.0f) ? (-b1 / w1) : 3.0e38f;
    key[tid] = t;
    idx[tid] = (unsigned)tid;

    // deterministic bitonic sort (identical across all CTAs of a channel)
    for (unsigned size = 2; size <= HID; size <<= 1) {
        for (unsigned stride = size >> 1; stride; stride >>= 1) {
            __syncthreads();
            unsigned partner = (unsigned)tid ^ stride;
            if (partner > (unsigned)tid) {
                bool up = ((tid & size) == 0);
                float k1 = key[tid], k2 = key[partner];
                if ((k1 > k2) == up) {
                    key[tid] = k2; key[partner] = k1;
                    unsigned v = idx[tid]; idx[tid] = idx[partner]; idx[partner] = v;
                }
            }
        }
    }
    __syncthreads();

    {
        unsigned h = idx[tid];
        float w = sw1[h], b = sb1[h];
        bool base = (w < 0.0f) || (w == 0.0f && b > 0.0f);
        sca0[tid] = base ? w : 0.0f;
        scb0[tid] = base ? b : 0.0f;
        float s = (w > 0.0f) ? 1.0f : ((w < 0.0f) ? -1.0f : 0.0f);
        sca1[tid] = s * w;
        scb1[tid] = s * b;

        if (g == 0) {                       // publish sort outputs for k_pseg
            g_t  [c][tid] = key[tid];
            g_idx[c][tid] = (int)h;
            g_ca1[c][tid] = sca1[tid];
            g_cb1[c][tid] = scb1[tid];
        }
    }
    __syncthreads();

    // group partial sums for group g (k = tid)
    int k = tid;
    float sbA = 0.f, sbB = 0.f, stA = 0.f, stB = 0.f;
    #pragma unroll
    for (int jj = 0; jj < GS; jj++) {
        int j = g * GS + jj;
        int h = (int)idx[j];
        float w2 = W2[(c * HID + h) * HID + k];
        sbA = fmaf(sca0[j], w2, sbA);
        sbB = fmaf(scb0[j], w2, sbB);
        stA = fmaf(sca1[j], w2, stA);
        stB = fmaf(scb1[j], w2, stB);
    }
    g_SbA[c][g][k] = sbA; g_SbB[c][g][k] = sbB;
    g_StA[c][g][k] = stA; g_StB[c][g][k] = stB;
}

// ---------------------------------------------------------------------------
// K2 fused: prefix rows in SMEM + warp-per-interval segment extraction
// ---------------------------------------------------------------------------
__global__ void __launch_bounds__(256) k_pseg(const float* __restrict__ W2,
                                              const float* __restrict__ B2,
                                              const float* __restrict__ W3,
                                              const float* __restrict__ B3)
{
    int g    = blockIdx.x;   // 0..15
    int c    = blockIdx.y;
    int tid  = threadIdx.x;
    int w    = tid >> 5;
    int lane = tid & 31;

    __shared__ float    sA [GS + 1][HID];
    __shared__ float    sB [GS + 1][HID];
    __shared__ float    sW3[HID][3];
    __shared__ float    sxc[8][SEG_CAP];
    __shared__ unsigned spay[8][SEG_CAP];

    // ---- Phase 1: prefix rows into SMEM (thread = k) ----
    {
        int k = tid;
        sW3[k][0] = W3[(c * HID + k) * 3 + 0];
        sW3[k][1] = W3[(c * HID + k) * 3 + 1];
        sW3[k][2] = W3[(c * HID + k) * 3 + 2];

        float A = 0.f;
        float B = B2[c * HID + k];
        #pragma unroll
        for (int g2 = 0; g2 < NG; g2++) {
            A += g_SbA[c][g2][k];
            B += g_SbB[c][g2][k];
        }
        for (int g2 = 0; g2 < g; g2++) {
            A += g_StA[c][g2][k];
            B += g_StB[c][g2][k];
        }
        sA[0][k] = A; sB[0][k] = B;

        #pragma unroll
        for (int jj = 0; jj < GS; jj++) {
            int j = g * GS + jj;
            int h = g_idx[c][j];
            float w2 = W2[(c * HID + h) * HID + k];
            A = fmaf(g_ca1[c][j], w2, A);
            B = fmaf(g_cb1[c][j], w2, B);
            sA[jj + 1][k] = A; sB[jj + 1][k] = B;
        }
    }
    __syncthreads();

    // ---- Phase 2: warp-per-interval ----
    float bQ0 = B3[c * 3 + 0], bQ1 = B3[c * 3 + 1], bQ2 = B3[c * 3 + 2];
    int nR = (g == NG - 1) ? (GS + 1) : GS;

    for (int r = w; r < nR; r += 8) {
        int i = g * GS + r;

        float lo = (i == 0)   ? -XMAXV : g_t[c][i - 1];
        float hi = (i == 256) ?  XMAXV : g_t[c][i];
        lo = fminf(fmaxf(lo, -XMAXV), XMAXV);
        hi = fminf(fmaxf(hi, -XMAXV), XMAXV);
        if (hi < lo) hi = lo;

        float acc0 = 0.f, acc1 = 0.f, acc2 = 0.f, acc3 = 0.f, acc4 = 0.f, acc5 = 0.f;
        int m = 0;

        #pragma unroll
        for (int q = 0; q < 8; q++) {
            int k = q * 32 + lane;
            float a  = sA[r][k];
            float bb = sB[r][k];

            float gl = fmaf(a, lo, bb);
            float gh = fmaf(a, hi, bb);
            if (gl > 0.0f) {
                float u0 = sW3[k][0], u1 = sW3[k][1], u2 = sW3[k][2];
                acc0 = fmaf(a,  u0, acc0); acc1 = fmaf(a,  u1, acc1); acc2 = fmaf(a,  u2, acc2);
                acc3 = fmaf(bb, u0, acc3); acc4 = fmaf(bb, u1, acc4); acc5 = fmaf(bb, u2, acc5);
            }
            bool has = ((gl > 0.0f) != (gh > 0.0f));
            unsigned mask = __ballot_sync(0xFFFFFFFFu, has);
            if (has) {
                int slot = m + __popc(mask & ((1u << lane) - 1u));
                if (slot < SEG_CAP) {
                    sxc [w][slot] = lo + (hi - lo) * (gl / (gl - gh));
                    spay[w][slot] = (unsigned)k | ((gh > 0.0f) ? 256u : 0u);
                }
            }
            m += __popc(mask);
        }

        #pragma unroll
        for (int off = 16; off; off >>= 1) {
            acc0 += __shfl_down_sync(0xFFFFFFFFu, acc0, off);
            acc1 += __shfl_down_sync(0xFFFFFFFFu, acc1, off);
            acc2 += __shfl_down_sync(0xFFFFFFFFu, acc2, off);
            acc3 += __shfl_down_sync(0xFFFFFFFFu, acc3, off);
            acc4 += __shfl_down_sync(0xFFFFFFFFu, acc4, off);
            acc5 += __shfl_down_sync(0xFFFFFFFFu, acc5, off);
        }
        float P0 = __shfl_sync(0xFFFFFFFFu, acc0, 0);
        float P1 = __shfl_sync(0xFFFFFFFFu, acc1, 0);
        float P2 = __shfl_sync(0xFFFFFFFFu, acc2, 0);
        float Q0 = __shfl_sync(0xFFFFFFFFu, acc3, 0) + bQ0;
        float Q1 = __shfl_sync(0xFFFFFFFFu, acc4, 0) + bQ1;
        float Q2 = __shfl_sync(0xFFFFFFFFu, acc5, 0) + bQ2;

        __syncwarp();

        if (lane == 0) {
            g_cnt[c][i] = m;
            float* pq = &g_PQ[c][i][0][0];
            pq[0] = P0; pq[1] = P1; pq[2] = P2; pq[3] = Q0; pq[4] = Q1; pq[5] = Q2;
        }

        if (m == 0) continue;

        if (m <= SEG_CAP) {
            bool  own = (lane < m);
            float xcL = own ? sxc[w][lane] : FLT_MAX;
            int   rk  = 0;
            float S0 = P0, S1 = P1, S2 = P2, S3 = Q0, S4 = Q1, S5 = Q2;
            for (int l2 = 0; l2 < m; l2++) {
                float o = sxc[w][l2];
                bool before = (o < xcL) || (o == xcL && l2 < lane);
                if (own && before) rk++;
                bool incl = own && (before || l2 == lane);
                if (incl) {
                    unsigned p = spay[w][l2];
                    int   kk = (int)(p & 255u);
                    float d  = (p & 256u) ? 1.0f : -1.0f;
                    float a  = d * sA[r][kk];
                    float bb = d * sB[r][kk];
                    float u0 = sW3[kk][0], u1 = sW3[kk][1], u2 = sW3[kk][2];
                    S0 = fmaf(a,  u0, S0); S1 = fmaf(a,  u1, S1); S2 = fmaf(a,  u2, S2);
                    S3 = fmaf(bb, u0, S3); S4 = fmaf(bb, u1, S4); S5 = fmaf(bb, u2, S5);
                }
            }
            if (own) {
                g_xc[c][i][rk] = xcL;
                float* pq = &g_PQ[c][i][rk + 1][0];
                pq[0] = S0; pq[1] = S1; pq[2] = S2; pq[3] = S3; pq[4] = S4; pq[5] = S5;
            }
        } else if (lane == 0) {
            float S0 = P0, S1 = P1, S2 = P2, S3 = Q0, S4 = Q1, S5 = Q2;
            float last = -FLT_MAX; int lastk = -1;
            for (int j = 0; j < m; j++) {
                float best = FLT_MAX; int bk = -1; float bd = 0.f;
                for (int k = 0; k < HID; k++) {
                    float a  = sA[r][k], bb = sB[r][k];
                    float gl = fmaf(a, lo, bb), gh = fmaf(a, hi, bb);
                    if ((gl > 0.0f) != (gh > 0.0f)) {
                        float xc = lo + (hi - lo) * (gl / (gl - gh));
                        bool gt = (xc > last) || (xc == last && k > lastk);
                        if (gt && (xc < best || (xc == best && k < bk))) {
                            best = xc; bk = k; bd = (gh > 0.0f) ? 1.0f : -1.0f;
                        }
                    }
                }
                last = best; lastk = bk;
                float a  = bd * sA[r][bk];
                float bb = bd * sB[r][bk];
                float u0 = sW3[bk][0], u1 = sW3[bk][1], u2 = sW3[bk][2];
                S0 = fmaf(a,  u0, S0); S1 = fmaf(a,  u1, S1); S2 = fmaf(a,  u2, S2);
                S3 = fmaf(bb, u0, S3); S4 = fmaf(bb, u1, S4); S5 = fmaf(bb, u2, S5);
                g_xc[c][i][j] = best;
                float* pq = &g_PQ[c][i][j + 1][0];
                pq[0] = S0; pq[1] = S1; pq[2] = S2; pq[3] = S3; pq[4] = S4; pq[5] = S5;
            }
        }
    }
}

// ---------------------------------------------------------------------------
// K_emit: per (interval-chunk, channel): redundant block scan + PARALLEL
// dense-segment emission (16 lanes per interval). Writes g_seg, g_segx, g_S.
// ---------------------------------------------------------------------------
__global__ void __launch_bounds__(256) k_emit()
{
    int q    = blockIdx.x;   // 0..16 (chunk of 16 intervals; q=16 -> i=256)
    int c    = blockIdx.y;
    int tid  = threadIdx.x;
    int lane = tid & 31;
    int warp = tid >> 5;

    __shared__ int sbase[NIV + 1];
    __shared__ int wsum[8];

    // parallel exclusive scan of (cnt+1) over intervals 0..255
    int v = g_cnt[c][tid] + 1;
    int incl = v;
    #pragma unroll
    for (int o = 1; o < 32; o <<= 1) {
        int n = __shfl_up_sync(0xFFFFFFFFu, incl, o);
        if (lane >= o) incl += n;
    }
    if (lane == 31) wsum[warp] = incl;
    __syncthreads();
    if (tid == 0) {
        int acc = 0;
        #pragma unroll
        for (int w2 = 0; w2 < 8; w2++) { int t2 = wsum[w2]; wsum[w2] = acc; acc += t2; }
    }
    __syncthreads();
    int excl = incl - v + wsum[warp];
    sbase[tid] = excl;
    if (tid == 255) {
        int b256 = excl + v;
        sbase[256] = b256;
        int Stot  = b256 + g_cnt[c][256] + 1;
        sbase[NIV] = Stot;
        g_S[c] = (Stot < SEGMAX) ? Stot : SEGMAX;
    }
    __syncthreads();

    // parallel emission: 16 lanes per interval
    int i   = q * 16 + (tid >> 4);
    int sub = tid & 15;
    if (i <= 256) {
        int m    = g_cnt[c][i];
        int base = sbase[i];
        for (int j = sub; j <= m; j += 16) {
            float xhi;
            if (j < m)        xhi = g_xc[c][i][j];
            else if (i < 256) xhi = g_t[c][i];
            else              xhi = FLT_MAX;
            int s = base + j;
            if (s < SEGMAX) {
                g_segx[c][s] = xhi;
                const float4* pq = (const float4*)&g_PQ[c][i][j][0];
                float4 p = pq[0];       // P0,P1,P2,Q0
                float4 qq = pq[1];      // Q1,Q2,-,-
                float4* dq = (float4*)&g_seg[c][s][0];
                dq[0] = make_float4(p.x, p.y, p.z, xhi);
                dq[1] = make_float4(p.w, qq.x, qq.y, 0.f);
            }
        }
    }
}

// ---------------------------------------------------------------------------
// K_buck: no SMEM. One bucket per thread; binary search g_segx directly in
// L2 (adjacent buckets share search paths -> broadcast loads). Coalesced
// fat-bucket stores.
// ---------------------------------------------------------------------------
__global__ void __launch_bounds__(256) k_buck()
{
    int c = blockIdx.y;
    int b = blockIdx.x * 256 + threadIdx.x;

    int S = g_S[c];
    const float* xr = &g_segx[c][0];

    float eb = BX0 + (float)b * (1.0f / BINVW);
    int lo = 0, hi = S - 1;
    while (lo < hi) {
        int mid = (lo + hi) >> 1;
        if (__ldg(xr + mid) <= eb) lo = mid + 1; else hi = mid;
    }
    if (b == 0) lo = 0;                 // pin bucket 0 to segment 0
    const float4* sp = (const float4*)&g_seg[c][lo][0];
    float4 s0 = sp[0];                  // P0,P1,P2,xhi
    float4 s1 = sp[1];                  // Q0,Q1,Q2,pad
    float4* dst = (float4*)&g_bk[c][b][0];
    dst[0] = s0;
    dst[1] = make_float4(s1.x, s1.y, s1.z, __int_as_float(lo));
}

// ---------------------------------------------------------------------------
// K3: evaluation. 2 evals/thread; pair-cooperative 32B bucket loads.
// ---------------------------------------------------------------------------
__global__ void __launch_bounds__(256) k_eval(const float* __restrict__ X,
                                              float* __restrict__ out)
{
    int t2   = blockIdx.x * 256 + threadIdx.x;   // group of 2 evals
    int lane = threadIdx.x & 31;
    int p0   = t2 * 2;
    int c0   = p0 & 15;                          // even, c0+1 <= 15
    bool odd = (lane & 1);

    float2 xv = ((const float2*)X)[t2];
    float xs[2] = {xv.x, xv.y};
    float r[6];

    #pragma unroll
    for (int e = 0; e < 2; e++) {
        float x = xs[e];
        int   c = c0 + e;
        int b = (int)((x - BX0) * BINVW);
        b = min(max(b, 0), NB - 1);
        const float* my = &g_bk[c][b][0];

        float xp = __shfl_xor_sync(0xFFFFFFFFu, x, 1);
        int   cp = (c0 ^ 2) + e;
        int   bp = (int)((xp - BX0) * BINVW);
        bp = min(max(bp, 0), NB - 1);
        const float* pa = &g_bk[cp][bp][0];

        float4 rA = *(const float4*)(odd ? pa + 4 : my);
        float4 rB = *(const float4*)(odd ? my + 4 : pa);

        float4 tA, tB;
        tA.x = __shfl_xor_sync(0xFFFFFFFFu, rA.x, 1);
        tA.y = __shfl_xor_sync(0xFFFFFFFFu, rA.y, 1);
        tA.z = __shfl_xor_sync(0xFFFFFFFFu, rA.z, 1);
        tA.w = __shfl_xor_sync(0xFFFFFFFFu, rA.w, 1);
        tB.x = __shfl_xor_sync(0xFFFFFFFFu, rB.x, 1);
        tB.y = __shfl_xor_sync(0xFFFFFFFFu, rB.y, 1);
        tB.z = __shfl_xor_sync(0xFFFFFFFFu, rB.z, 1);
        tB.w = __shfl_xor_sync(0xFFFFFFFFu, rB.w, 1);

        float4 a = odd ? tB : rA;   // P0,P1,P2,xhi  of OWN eval
        float4 q = odd ? rB : tA;   // Q0,Q1,Q2,j    of OWN eval

        if (x >= a.w) {             // fallback: walk self-contained segments
            int j = __float_as_int(q.w);
            float4 s0, s1;
            do {
                ++j;
                const float4* sp = (const float4*)&g_seg[c][j][0];
                s0 = sp[0];
                s1 = sp[1];
            } while (x >= s0.w);
            a = s0; q = s1;
        }
        r[e * 3 + 0] = fmaf(a.x, x, q.x);
        r[e * 3 + 1] = fmaf(a.y, x, q.y);
        r[e * 3 + 2] = fmaf(a.z, x, q.z);
    }

    float2* ob = (float2*)(out + (size_t)t2 * 6);
    ob[0] = make_float2(r[0], r[1]);
    ob[1] = make_float2(r[2], r[3]);
    ob[2] = make_float2(r[4], r[5]);
}

// ---------------------------------------------------------------------------
extern "C" void kernel_launch(void* const* d_in, const int* in_sizes, int n_in,
                              void* d_out, int out_size)
{
    const float* x  = (const float*)d_in[0];
    const float* W1 = (const float*)d_in[1];
    const float* b1 = (const float*)d_in[2];
    const float* W2 = (const float*)d_in[3];
    const float* b2 = (const float*)d_in[4];
    const float* W3 = (const float*)d_in[5];
    const float* b3 = (const float*)d_in[6];
    float* out = (float*)d_out;

    k_gs  <<<dim3(NG, CHN), 256>>>(W1, b1, W2);
    k_pseg<<<dim3(NG, CHN), 256>>>(W2, b2, W3, b3);
    k_emit<<<dim3(17, CHN), 256>>>();
    k_buck<<<dim3(NB / 256, CHN), 256>>>();
    k_eval<<<(32768 * CHN) / (256 * 2), 256>>>(x, out);
}

// round 17
// speedup vs baseline: 1.0821x; 1.0821x over previous
#include <cuda_runtime.h>
#include <float.h>

// ============================================================================
// KolmogorovArnoldNetwork: exact piecewise-linear reformulation.
// R17: revert to R14 (best 31.2us); NB 8192 -> 4096 (width 2^-8, exact
//      edges): k_buck work halves along the measured NB slope, eval straddle
//      rate ~doubles (cheap). k_buck = SMEM-staged full-parallel search.
// Pipeline: k_gs(16x16) -> k_pseg(16x16) -> k_emit(17x16) -> k_buck(16x16)
//           -> k_eval(1024)
// ============================================================================

#define CHN    16
#define HID    256
#define NIV    257
#define XMAXV  64.0f
#define NG     16
#define GS     16
#define SEG_CAP 32
#define SEGMAX 8192
#define NB     4096
#define BX0    (-8.0f)
#define BINVW  256.0f       // NB / 16 range; bucket width = 2^-8 (exact)

// Scratch (device globals; no allocation)
__device__ float g_t   [CHN][HID];
__device__ int   g_idx [CHN][HID];
__device__ float g_ca1 [CHN][HID];
__device__ float g_cb1 [CHN][HID];
__device__ float g_SbA [CHN][NG][HID];
__device__ float g_SbB [CHN][NG][HID];
__device__ float g_StA [CHN][NG][HID];
__device__ float g_StB [CHN][NG][HID];
__device__ int   g_cnt [CHN][NIV];
__device__ float g_xc  [CHN][NIV][NIV];
__device__ __align__(16) float g_PQ[CHN][NIV][NIV][8];
// dense self-contained segments: {P0,P1,P2,xhi, Q0,Q1,Q2,pad}
__device__ __align__(16) float g_seg[CHN][SEGMAX][8];
__device__ float g_segx[CHN][SEGMAX];
__device__ int   g_S   [CHN];
// fat buckets: {P0,P1,P2,xhi, Q0,Q1,Q2,j_as_int_bits}
__device__ __align__(16) float g_bk[CHN][NB][8];

// ---------------------------------------------------------------------------
// K1: per (group, channel): redundant bitonic sort + this group's partials
// ---------------------------------------------------------------------------
__global__ void __launch_bounds__(256) k_gs(const float* __restrict__ W1,
                                            const float* __restrict__ B1,
                                            const float* __restrict__ W2)
{
    int g   = blockIdx.x;
    int c   = blockIdx.y;
    int tid = threadIdx.x;

    __shared__ float    key[HID];
    __shared__ unsigned idx[HID];
    __shared__ float    sw1[HID], sb1[HID];
    __shared__ float    sca0[HID], scb0[HID], sca1[HID], scb1[HID];

    float w1 = W1[c * HID + tid];
    float b1 = B1[c * HID + tid];
    sw1[tid] = w1; sb1[tid] = b1;

    float t = (w1 != 0.0f) ? (-b1 / w1) : 3.0e38f;
    key[tid] = t;
    idx[tid] = (unsigned)tid;

    // deterministic bitonic sort (identical across all CTAs of a channel)
    for (unsigned size = 2; size <= HID; size <<= 1) {
        for (unsigned stride = size >> 1; stride; stride >>= 1) {
            __syncthreads();
            unsigned partner = (unsigned)tid ^ stride;
            if (partner > (unsigned)tid) {
                bool up = ((tid & size) == 0);
                float k1 = key[tid], k2 = key[partner];
                if ((k1 > k2) == up) {
                    key[tid] = k2; key[partner] = k1;
                    unsigned v = idx[tid]; idx[tid] = idx[partner]; idx[partner] = v;
                }
            }
        }
    }
    __syncthreads();

    {
        unsigned h = idx[tid];
        float w = sw1[h], b = sb1[h];
        bool base = (w < 0.0f) || (w == 0.0f && b > 0.0f);
        sca0[tid] = base ? w : 0.0f;
        scb0[tid] = base ? b : 0.0f;
        float s = (w > 0.0f) ? 1.0f : ((w < 0.0f) ? -1.0f : 0.0f);
        sca1[tid] = s * w;
        scb1[tid] = s * b;

        if (g == 0) {                       // publish sort outputs for k_pseg
            g_t  [c][tid] = key[tid];
            g_idx[c][tid] = (int)h;
            g_ca1[c][tid] = sca1[tid];
            g_cb1[c][tid] = scb1[tid];
        }
    }
    __syncthreads();

    // group partial sums for group g (k = tid)
    int k = tid;
    float sbA = 0.f, sbB = 0.f, stA = 0.f, stB = 0.f;
    #pragma unroll
    for (int jj = 0; jj < GS; jj++) {
        int j = g * GS + jj;
        int h = (int)idx[j];
        float w2 = W2[(c * HID + h) * HID + k];
        sbA = fmaf(sca0[j], w2, sbA);
        sbB = fmaf(scb0[j], w2, sbB);
        stA = fmaf(sca1[j], w2, stA);
        stB = fmaf(scb1[j], w2, stB);
    }
    g_SbA[c][g][k] = sbA; g_SbB[c][g][k] = sbB;
    g_StA[c][g][k] = stA; g_StB[c][g][k] = stB;
}

// ---------------------------------------------------------------------------
// K2 fused: prefix rows in SMEM + warp-per-interval segment extraction
// ---------------------------------------------------------------------------
__global__ void __launch_bounds__(256) k_pseg(const float* __restrict__ W2,
                                              const float* __restrict__ B2,
                                              const float* __restrict__ W3,
                                              const float* __restrict__ B3)
{
    int g    = blockIdx.x;   // 0..15
    int c    = blockIdx.y;
    int tid  = threadIdx.x;
    int w    = tid >> 5;
    int lane = tid & 31;

    __shared__ float    sA [GS + 1][HID];
    __shared__ float    sB [GS + 1][HID];
    __shared__ float    sW3[HID][3];
    __shared__ float    sxc[8][SEG_CAP];
    __shared__ unsigned spay[8][SEG_CAP];

    // ---- Phase 1: prefix rows into SMEM (thread = k) ----
    {
        int k = tid;
        sW3[k][0] = W3[(c * HID + k) * 3 + 0];
        sW3[k][1] = W3[(c * HID + k) * 3 + 1];
        sW3[k][2] = W3[(c * HID + k) * 3 + 2];

        float A = 0.f;
        float B = B2[c * HID + k];
        #pragma unroll
        for (int g2 = 0; g2 < NG; g2++) {
            A += g_SbA[c][g2][k];
            B += g_SbB[c][g2][k];
        }
        for (int g2 = 0; g2 < g; g2++) {
            A += g_StA[c][g2][k];
            B += g_StB[c][g2][k];
        }
        sA[0][k] = A; sB[0][k] = B;

        #pragma unroll
        for (int jj = 0; jj < GS; jj++) {
            int j = g * GS + jj;
            int h = g_idx[c][j];
            float w2 = W2[(c * HID + h) * HID + k];
            A = fmaf(g_ca1[c][j], w2, A);
            B = fmaf(g_cb1[c][j], w2, B);
            sA[jj + 1][k] = A; sB[jj + 1][k] = B;
        }
    }
    __syncthreads();

    // ---- Phase 2: warp-per-interval ----
    float bQ0 = B3[c * 3 + 0], bQ1 = B3[c * 3 + 1], bQ2 = B3[c * 3 + 2];
    int nR = (g == NG - 1) ? (GS + 1) : GS;

    for (int r = w; r < nR; r += 8) {
        int i = g * GS + r;

        float lo = (i == 0)   ? -XMAXV : g_t[c][i - 1];
        float hi = (i == 256) ?  XMAXV : g_t[c][i];
        lo = fminf(fmaxf(lo, -XMAXV), XMAXV);
        hi = fminf(fmaxf(hi, -XMAXV), XMAXV);
        if (hi < lo) hi = lo;

        float acc0 = 0.f, acc1 = 0.f, acc2 = 0.f, acc3 = 0.f, acc4 = 0.f, acc5 = 0.f;
        int m = 0;

        #pragma unroll
        for (int q = 0; q < 8; q++) {
            int k = q * 32 + lane;
            float a  = sA[r][k];
            float bb = sB[r][k];

            float gl = fmaf(a, lo, bb);
            float gh = fmaf(a, hi, bb);
            if (gl > 0.0f) {
                float u0 = sW3[k][0], u1 = sW3[k][1], u2 = sW3[k][2];
                acc0 = fmaf(a,  u0, acc0); acc1 = fmaf(a,  u1, acc1); acc2 = fmaf(a,  u2, acc2);
                acc3 = fmaf(bb, u0, acc3); acc4 = fmaf(bb, u1, acc4); acc5 = fmaf(bb, u2, acc5);
            }
            bool has = ((gl > 0.0f) != (gh > 0.0f));
            unsigned mask = __ballot_sync(0xFFFFFFFFu, has);
            if (has) {
                int slot = m + __popc(mask & ((1u << lane) - 1u));
                if (slot < SEG_CAP) {
                    sxc [w][slot] = lo + (hi - lo) * (gl / (gl - gh));
                    spay[w][slot] = (unsigned)k | ((gh > 0.0f) ? 256u : 0u);
                }
            }
            m += __popc(mask);
        }

        #pragma unroll
        for (int off = 16; off; off >>= 1) {
            acc0 += __shfl_down_sync(0xFFFFFFFFu, acc0, off);
            acc1 += __shfl_down_sync(0xFFFFFFFFu, acc1, off);
            acc2 += __shfl_down_sync(0xFFFFFFFFu, acc2, off);
            acc3 += __shfl_down_sync(0xFFFFFFFFu, acc3, off);
            acc4 += __shfl_down_sync(0xFFFFFFFFu, acc4, off);
            acc5 += __shfl_down_sync(0xFFFFFFFFu, acc5, off);
        }
        float P0 = __shfl_sync(0xFFFFFFFFu, acc0, 0);
        float P1 = __shfl_sync(0xFFFFFFFFu, acc1, 0);
        float P2 = __shfl_sync(0xFFFFFFFFu, acc2, 0);
        float Q0 = __shfl_sync(0xFFFFFFFFu, acc3, 0) + bQ0;
        float Q1 = __shfl_sync(0xFFFFFFFFu, acc4, 0) + bQ1;
        float Q2 = __shfl_sync(0xFFFFFFFFu, acc5, 0) + bQ2;

        __syncwarp();

        if (lane == 0) {
            g_cnt[c][i] = m;
            float* pq = &g_PQ[c][i][0][0];
            pq[0] = P0; pq[1] = P1; pq[2] = P2; pq[3] = Q0; pq[4] = Q1; pq[5] = Q2;
        }

        if (m == 0) continue;

        if (m <= SEG_CAP) {
            bool  own = (lane < m);
            float xcL = own ? sxc[w][lane] : FLT_MAX;
            int   rk  = 0;
            float S0 = P0, S1 = P1, S2 = P2, S3 = Q0, S4 = Q1, S5 = Q2;
            for (int l2 = 0; l2 < m; l2++) {
                float o = sxc[w][l2];
                bool before = (o < xcL) || (o == xcL && l2 < lane);
                if (own && before) rk++;
                bool incl = own && (before || l2 == lane);
                if (incl) {
                    unsigned p = spay[w][l2];
                    int   kk = (int)(p & 255u);
                    float d  = (p & 256u) ? 1.0f : -1.0f;
                    float a  = d * sA[r][kk];
                    float bb = d * sB[r][kk];
                    float u0 = sW3[kk][0], u1 = sW3[kk][1], u2 = sW3[kk][2];
                    S0 = fmaf(a,  u0, S0); S1 = fmaf(a,  u1, S1); S2 = fmaf(a,  u2, S2);
                    S3 = fmaf(bb, u0, S3); S4 = fmaf(bb, u1, S4); S5 = fmaf(bb, u2, S5);
                }
            }
            if (own) {
                g_xc[c][i][rk] = xcL;
                float* pq = &g_PQ[c][i][rk + 1][0];
                pq[0] = S0; pq[1] = S1; pq[2] = S2; pq[3] = S3; pq[4] = S4; pq[5] = S5;
            }
        } else if (lane == 0) {
            float S0 = P0, S1 = P1, S2 = P2, S3 = Q0, S4 = Q1, S5 = Q2;
            float last = -FLT_MAX; int lastk = -1;
            for (int j = 0; j < m; j++) {
                float best = FLT_MAX; int bk = -1; float bd = 0.f;
                for (int k = 0; k < HID; k++) {
                    float a  = sA[r][k], bb = sB[r][k];
                    float gl = fmaf(a, lo, bb), gh = fmaf(a, hi, bb);
                    if ((gl > 0.0f) != (gh > 0.0f)) {
                        float xc = lo + (hi - lo) * (gl / (gl - gh));
                        bool gt = (xc > last) || (xc == last && k > lastk);
                        if (gt && (xc < best || (xc == best && k < bk))) {
                            best = xc; bk = k; bd = (gh > 0.0f) ? 1.0f : -1.0f;
                        }
                    }
                }
                last = best; lastk = bk;
                float a  = bd * sA[r][bk];
                float bb = bd * sB[r][bk];
                float u0 = sW3[bk][0], u1 = sW3[bk][1], u2 = sW3[bk][2];
                S0 = fmaf(a,  u0, S0); S1 = fmaf(a,  u1, S1); S2 = fmaf(a,  u2, S2);
                S3 = fmaf(bb, u0, S3); S4 = fmaf(bb, u1, S4); S5 = fmaf(bb, u2, S5);
                g_xc[c][i][j] = best;
                float* pq = &g_PQ[c][i][j + 1][0];
                pq[0] = S0; pq[1] = S1; pq[2] = S2; pq[3] = S3; pq[4] = S4; pq[5] = S5;
            }
        }
    }
}

// ---------------------------------------------------------------------------
// K_emit: per (interval-chunk, channel): redundant block scan + PARALLEL
// dense-segment emission (16 lanes per interval). Writes g_seg, g_segx, g_S.
// ---------------------------------------------------------------------------
__global__ void __launch_bounds__(256) k_emit()
{
    int q    = blockIdx.x;   // 0..16 (chunk of 16 intervals; q=16 -> i=256)
    int c    = blockIdx.y;
    int tid  = threadIdx.x;
    int lane = tid & 31;
    int warp = tid >> 5;

    __shared__ int sbase[NIV + 1];
    __shared__ int wsum[8];

    // parallel exclusive scan of (cnt+1) over intervals 0..255
    int v = g_cnt[c][tid] + 1;
    int incl = v;
    #pragma unroll
    for (int o = 1; o < 32; o <<= 1) {
        int n = __shfl_up_sync(0xFFFFFFFFu, incl, o);
        if (lane >= o) incl += n;
    }
    if (lane == 31) wsum[warp] = incl;
    __syncthreads();
    if (tid == 0) {
        int acc = 0;
        #pragma unroll
        for (int w2 = 0; w2 < 8; w2++) { int t2 = wsum[w2]; wsum[w2] = acc; acc += t2; }
    }
    __syncthreads();
    int excl = incl - v + wsum[warp];
    sbase[tid] = excl;
    if (tid == 255) {
        int b256 = excl + v;
        sbase[256] = b256;
        int Stot  = b256 + g_cnt[c][256] + 1;
        sbase[NIV] = Stot;
        g_S[c] = (Stot < SEGMAX) ? Stot : SEGMAX;
    }
    __syncthreads();

    // parallel emission: 16 lanes per interval
    int i   = q * 16 + (tid >> 4);
    int sub = tid & 15;
    if (i <= 256) {
        int m    = g_cnt[c][i];
        int base = sbase[i];
        for (int j = sub; j <= m; j += 16) {
            float xhi;
            if (j < m)        xhi = g_xc[c][i][j];
            else if (i < 256) xhi = g_t[c][i];
            else              xhi = FLT_MAX;
            int s = base + j;
            if (s < SEGMAX) {
                g_segx[c][s] = xhi;
                const float4* pq = (const float4*)&g_PQ[c][i][j][0];
                float4 p = pq[0];       // P0,P1,P2,Q0
                float4 qq = pq[1];      // Q1,Q2,-,-
                float4* dq = (float4*)&g_seg[c][s][0];
                dq[0] = make_float4(p.x, p.y, p.z, xhi);
                dq[1] = make_float4(p.w, qq.x, qq.y, 0.f);
            }
        }
    }
}

// ---------------------------------------------------------------------------
// K_buck: per (chunk, channel): 256 buckets, ONE per thread. SMEM sxhi,
// full-parallel binary search; coalesced fat-bucket stores.
// ---------------------------------------------------------------------------
__global__ void __launch_bounds__(256) k_buck()
{
    int chunk = blockIdx.x;   // 0..15
    int c     = blockIdx.y;
    int tid   = threadIdx.x;

    __shared__ float sxhi[SEGMAX];
    __shared__ int   sS;

    if (tid == 0) sS = g_S[c];
    __syncthreads();
    int S = sS;
    for (int s = tid; s < S; s += 256) sxhi[s] = g_segx[c][s];
    __syncthreads();

    int b = chunk * 256 + tid;
    float eb = BX0 + (float)b * (1.0f / BINVW);
    int lo = 0, hi = S - 1;
    while (lo < hi) {
        int mid = (lo + hi) >> 1;
        if (sxhi[mid] <= eb) lo = mid + 1; else hi = mid;
    }
    if (b == 0) lo = 0;                 // pin bucket 0 to segment 0
    const float4* sp = (const float4*)&g_seg[c][lo][0];
    float4 s0 = sp[0];                  // P0,P1,P2,xhi
    float4 s1 = sp[1];                  // Q0,Q1,Q2,pad
    float4* dst = (float4*)&g_bk[c][b][0];
    dst[0] = s0;
    dst[1] = make_float4(s1.x, s1.y, s1.z, __int_as_float(lo));
}

// ---------------------------------------------------------------------------
// K3: evaluation. 2 evals/thread; pair-cooperative 32B bucket loads.
// ---------------------------------------------------------------------------
__global__ void __launch_bounds__(256) k_eval(const float* __restrict__ X,
                                              float* __restrict__ out)
{
    int t2   = blockIdx.x * 256 + threadIdx.x;   // group of 2 evals
    int lane = threadIdx.x & 31;
    int p0   = t2 * 2;
    int c0   = p0 & 15;                          // even, c0+1 <= 15
    bool odd = (lane & 1);

    float2 xv = ((const float2*)X)[t2];
    float xs[2] = {xv.x, xv.y};
    float r[6];

    #pragma unroll
    for (int e = 0; e < 2; e++) {
        float x = xs[e];
        int   c = c0 + e;
        int b = (int)((x - BX0) * BINVW);
        b = min(max(b, 0), NB - 1);
        const float* my = &g_bk[c][b][0];

        float xp = __shfl_xor_sync(0xFFFFFFFFu, x, 1);
        int   cp = (c0 ^ 2) + e;
        int   bp = (int)((xp - BX0) * BINVW);
        bp = min(max(bp, 0), NB - 1);
        const float* pa = &g_bk[cp][bp][0];

        float4 rA = *(const float4*)(odd ? pa + 4 : my);
        float4 rB = *(const float4*)(odd ? my + 4 : pa);

        float4 tA, tB;
        tA.x = __shfl_xor_sync(0xFFFFFFFFu, rA.x, 1);
        tA.y = __shfl_xor_sync(0xFFFFFFFFu, rA.y, 1);
        tA.z = __shfl_xor_sync(0xFFFFFFFFu, rA.z, 1);
        tA.w = __shfl_xor_sync(0xFFFFFFFFu, rA.w, 1);
        tB.x = __shfl_xor_sync(0xFFFFFFFFu, rB.x, 1);
        tB.y = __shfl_xor_sync(0xFFFFFFFFu, rB.y, 1);
        tB.z = __shfl_xor_sync(0xFFFFFFFFu, rB.z, 1);
        tB.w = __shfl_xor_sync(0xFFFFFFFFu, rB.w, 1);

        float4 a = odd ? tB : rA;   // P0,P1,P2,xhi  of OWN eval
        float4 q = odd ? rB : tA;   // Q0,Q1,Q2,j    of OWN eval

        if (x >= a.w) {             // fallback: walk self-contained segments
            int j = __float_as_int(q.w);
            float4 s0, s1;
            do {
                ++j;
                const float4* sp = (const float4*)&g_seg[c][j][0];
                s0 = sp[0];
                s1 = sp[1];
            } while (x >= s0.w);
            a = s0; q = s1;
        }
        r[e * 3 + 0] = fmaf(a.x, x, q.x);
        r[e * 3 + 1] = fmaf(a.y, x, q.y);
        r[e * 3 + 2] = fmaf(a.z, x, q.z);
    }

    float2* ob = (float2*)(out + (size_t)t2 * 6);
    ob[0] = make_float2(r[0], r[1]);
    ob[1] = make_float2(r[2], r[3]);
    ob[2] = make_float2(r[4], r[5]);
}

// ---------------------------------------------------------------------------
extern "C" void kernel_launch(void* const* d_in, const int* in_sizes, int n_in,
                              void* d_out, int out_size)
{
    const float* x  = (const float*)d_in[0];
    const float* W1 = (const float*)d_in[1];
    const float* b1 = (const float*)d_in[2];
    const float* W2 = (const float*)d_in[3];
    const float* b2 = (const float*)d_in[4];
    const float* W3 = (const float*)d_in[5];
    const float* b3 = (const float*)d_in[6];
    float* out = (float*)d_out;

    k_gs  <<<dim3(NG, CHN), 256>>>(W1, b1, W2);
    k_pseg<<<dim3(NG, CHN), 256>>>(W2, b2, W3, b3);
    k_emit<<<dim3(17, CHN), 256>>>();
    k_buck<<<dim3(NB / 256, CHN), 256>>>();
    k_eval<<<(32768 * CHN) / (256 * 2), 256>>>(x, out);
}